// round 1
// baseline (speedup 1.0000x reference)
#include <cuda_runtime.h>
#include <math.h>

// ---------------- problem constants ----------------
#define BB   128
#define TT   256
#define CC   384
#define HH   4
#define HSS  64
#define LL   6
#define VV   65
#define FFF  1536
#define NT   (BB*TT)      // 32768 tokens
#define HQ   (HH*HSS)     // 256

// ---------------- device scratch (no allocations allowed) ----------------
__device__ float g_x   [NT*CC];          // residual stream
__device__ float g_xn  [NT*CC];          // layernorm output
__device__ float g_qkv [NT*3*HQ];        // packed q|k|v per token
__device__ float g_att [NT*HQ];          // attention output (b,t,h,d)
__device__ float g_h   [NT*FFF];         // FF hidden
__device__ float g_wqkv[LL*CC*3*HQ];     // repacked qkv weights [l][c][n]
__device__ float g_nll [NT];             // per-token nll

// ---------------- embedding ----------------
__global__ void k_embed(const int* __restrict__ idx,
                        const float* __restrict__ tok,
                        const float* __restrict__ pos) {
    int i = blockIdx.x * blockDim.x + threadIdx.x;
    if (i >= NT*CC) return;
    int n = i / CC, c = i % CC;
    int t = n % TT;
    g_x[i] = tok[(size_t)idx[n]*CC + c] + pos[t*CC + c];
}

// ---------------- repack Wq/Wk/Wv (L,H,C,HS) -> [l][c][768] ----------------
__global__ void k_repack(const float* __restrict__ Wq,
                         const float* __restrict__ Wk,
                         const float* __restrict__ Wv) {
    int i = blockIdx.x * blockDim.x + threadIdx.x;
    if (i >= LL*CC*3*HQ) return;
    int n = i % (3*HQ);
    int c = (i / (3*HQ)) % CC;
    int l = i / (3*HQ*CC);
    const float* W = (n < HQ) ? Wq : (n < 2*HQ ? Wk : Wv);
    int nn = n % HQ;
    int h = nn / HSS, d = nn % HSS;
    g_wqkv[i] = W[(( (size_t)l*HH + h)*CC + c)*HSS + d];
}

// ---------------- layernorm: one warp per row of CC=384 ----------------
__global__ void k_ln(const float* __restrict__ in, float* __restrict__ out,
                     const float* __restrict__ g, const float* __restrict__ b) {
    int warp = (blockIdx.x * blockDim.x + threadIdx.x) >> 5;
    int lane = threadIdx.x & 31;
    if (warp >= NT) return;
    const float* row = in + (size_t)warp * CC;
    float s = 0.f, s2 = 0.f;
    for (int c = lane; c < CC; c += 32) { float v = row[c]; s += v; s2 += v*v; }
    #pragma unroll
    for (int o = 16; o; o >>= 1) {
        s  += __shfl_xor_sync(0xFFFFFFFFu, s,  o);
        s2 += __shfl_xor_sync(0xFFFFFFFFu, s2, o);
    }
    float mu  = s  * (1.f/CC);
    float var = s2 * (1.f/CC) - mu*mu;
    float r   = rsqrtf(var + 1e-5f);
    float* orow = out + (size_t)warp * CC;
    for (int c = lane; c < CC; c += 32)
        orow[c] = (row[c] - mu) * r * g[c] + b[c];
}

// ---------------- SGEMM: C[M,N] = A[M,K] @ B[K,N] (+bias)(+relu)(+resid) -----
// 128x64 tile, BK=16, 256 threads, 8x4 per thread.
template<int BIAS, int RELU, int RESID, int GN>
__global__ __launch_bounds__(256)
void k_gemm(const float* __restrict__ A, const float* __restrict__ Bm,
            const float* __restrict__ bias, const float* __restrict__ resid,
            float* __restrict__ Cm, int M, int N, int K) {
    __shared__ float As[16][129];   // [k][m], padded
    __shared__ float Bs[16][64];    // [k][n]
    const int tid = threadIdx.x;
    const int bm = blockIdx.y * 128;
    const int bn = blockIdx.x * 64;
    const int tx = tid & 15;        // n: 16 * 4 = 64
    const int ty = tid >> 4;        // m: 16 * 8 = 128
    float acc[8][4];
    #pragma unroll
    for (int i = 0; i < 8; i++)
        #pragma unroll
        for (int j = 0; j < 4; j++) acc[i][j] = 0.f;

    for (int k0 = 0; k0 < K; k0 += 16) {
        #pragma unroll
        for (int i = 0; i < 8; i++) {
            int idx = tid + i*256;
            int r = idx >> 4, c = idx & 15;
            As[c][r] = A[(size_t)(bm + r) * K + k0 + c];
        }
        #pragma unroll
        for (int i = 0; i < 4; i++) {
            int idx = tid + i*256;
            int r = idx >> 6, c = idx & 63;
            float v = 0.f;
            if (!GN || (bn + c) < N) v = Bm[(size_t)(k0 + r) * N + bn + c];
            Bs[r][c] = v;
        }
        __syncthreads();
        #pragma unroll
        for (int kk = 0; kk < 16; kk++) {
            float a[8], b[4];
            #pragma unroll
            for (int i = 0; i < 8; i++) a[i] = As[kk][ty*8 + i];
            #pragma unroll
            for (int j = 0; j < 4; j++) b[j] = Bs[kk][tx*4 + j];
            #pragma unroll
            for (int i = 0; i < 8; i++)
                #pragma unroll
                for (int j = 0; j < 4; j++) acc[i][j] += a[i] * b[j];
        }
        __syncthreads();
    }
    #pragma unroll
    for (int i = 0; i < 8; i++) {
        int m = bm + ty*8 + i;
        #pragma unroll
        for (int j = 0; j < 4; j++) {
            int n = bn + tx*4 + j;
            if (GN && n >= N) continue;
            float v = acc[i][j];
            if (BIAS)  v += bias[n];
            if (RELU)  v = fmaxf(v, 0.f);
            if (RESID) v += resid[(size_t)m * N + n];
            Cm[(size_t)m * N + n] = v;
        }
    }
}

// ---------------- causal attention: block per (b,h), thread per query t -----
__global__ __launch_bounds__(256)
void k_attn() {
    const int bh = blockIdx.x;
    const int b = bh / HH, h = bh % HH;
    const int t = threadIdx.x;
    __shared__ float Ks[64][64];
    __shared__ float Vs[64][64];
    const float scale = 0.125f;     // HS^-0.5

    float q[64];
    const float* qrow = g_qkv + (size_t)(b*TT + t) * (3*HQ) + h*HSS;
    #pragma unroll
    for (int d = 0; d < 64; d++) q[d] = qrow[d] * scale;

    float o[64];
    #pragma unroll
    for (int d = 0; d < 64; d++) o[d] = 0.f;
    float m = -1e30f, lsum = 0.f;

    for (int s0 = 0; s0 < TT; s0 += 64) {
        #pragma unroll
        for (int i = 0; i < 16; i++) {
            int idx = t + i*256;
            int r = idx >> 6, c = idx & 63;
            const float* base = g_qkv + (size_t)(b*TT + s0 + r) * (3*HQ) + h*HSS + c;
            Ks[r][c] = base[HQ];
            Vs[r][c] = base[2*HQ];
        }
        __syncthreads();
        if (t >= s0) {
            int send = min(64, t - s0 + 1);
            for (int s = 0; s < send; s++) {
                float sc = 0.f;
                #pragma unroll
                for (int d = 0; d < 64; d++) sc += q[d] * Ks[s][d];
                float mnew = fmaxf(m, sc);
                float corr = __expf(m - mnew);
                float p    = __expf(sc - mnew);
                lsum = lsum * corr + p;
                #pragma unroll
                for (int d = 0; d < 64; d++) o[d] = o[d] * corr + p * Vs[s][d];
                m = mnew;
            }
        }
        __syncthreads();
    }
    float inv = 1.f / lsum;
    float* orow = g_att + (size_t)(b*TT + t) * HQ + h*HSS;
    #pragma unroll
    for (int d = 0; d < 64; d++) orow[d] = o[d] * inv;
}

// ---------------- per-token NLL: warp per row of VV=65 logits ----------------
__global__ void k_nll(const float* __restrict__ logits, const int* __restrict__ tgt) {
    int warp = (blockIdx.x * blockDim.x + threadIdx.x) >> 5;
    int lane = threadIdx.x & 31;
    if (warp >= NT) return;
    const float* row = logits + (size_t)warp * VV;
    float mx = -1e30f;
    for (int v = lane; v < VV; v += 32) mx = fmaxf(mx, row[v]);
    #pragma unroll
    for (int o = 16; o; o >>= 1) mx = fmaxf(mx, __shfl_xor_sync(0xFFFFFFFFu, mx, o));
    float s = 0.f;
    for (int v = lane; v < VV; v += 32) s += expf(row[v] - mx);
    #pragma unroll
    for (int o = 16; o; o >>= 1) s += __shfl_xor_sync(0xFFFFFFFFu, s, o);
    if (lane == 0) {
        float lse = logf(s) + mx;
        g_nll[warp] = lse - row[tgt[warp]];
    }
}

__global__ void k_loss(float* __restrict__ out, int write_idx) {
    __shared__ float sh[256];
    float s = 0.f;
    for (int i = threadIdx.x; i < NT; i += 256) s += g_nll[i];
    sh[threadIdx.x] = s;
    __syncthreads();
    for (int o = 128; o; o >>= 1) {
        if (threadIdx.x < o) sh[threadIdx.x] += sh[threadIdx.x + o];
        __syncthreads();
    }
    if (threadIdx.x == 0) out[write_idx] = sh[0] / (float)NT;
}

// ---------------- launch ----------------
extern "C" void kernel_launch(void* const* d_in, const int* in_sizes, int n_in,
                              void* d_out, int out_size) {
    const int*   idx  = (const int*)  d_in[0];
    const int*   tgt  = (const int*)  d_in[1];
    const float* tok  = (const float*)d_in[2];
    const float* pos  = (const float*)d_in[3];
    const float* Wq   = (const float*)d_in[4];
    const float* Wk   = (const float*)d_in[5];
    const float* Wv   = (const float*)d_in[6];
    const float* Wo   = (const float*)d_in[7];
    const float* bo   = (const float*)d_in[8];
    const float* W1   = (const float*)d_in[9];
    const float* b1   = (const float*)d_in[10];
    const float* W2   = (const float*)d_in[11];
    const float* b2   = (const float*)d_in[12];
    const float* ln1g = (const float*)d_in[13];
    const float* ln1b = (const float*)d_in[14];
    const float* ln2g = (const float*)d_in[15];
    const float* ln2b = (const float*)d_in[16];
    const float* lnfg = (const float*)d_in[17];
    const float* lnfb = (const float*)d_in[18];
    const float* Wlm  = (const float*)d_in[19];
    const float* blm  = (const float*)d_in[20];
    float* out = (float*)d_out;

    float *px, *pxn, *pqkv, *patt, *ph, *pw;
    cudaGetSymbolAddress((void**)&px,   g_x);
    cudaGetSymbolAddress((void**)&pxn,  g_xn);
    cudaGetSymbolAddress((void**)&pqkv, g_qkv);
    cudaGetSymbolAddress((void**)&patt, g_att);
    cudaGetSymbolAddress((void**)&ph,   g_h);
    cudaGetSymbolAddress((void**)&pw,   g_wqkv);

    k_embed <<<(NT*CC + 255)/256, 256>>>(idx, tok, pos);
    k_repack<<<(LL*CC*3*HQ + 255)/256, 256>>>(Wq, Wk, Wv);

    for (int l = 0; l < LL; l++) {
        k_ln<<<NT/8, 256>>>(px, pxn, ln1g + l*CC, ln1b + l*CC);
        // qkv: [NT,384] @ [384,768]
        k_gemm<0,0,0,0><<<dim3(768/64, NT/128), 256>>>(
            pxn, pw + (size_t)l*CC*3*HQ, nullptr, nullptr, pqkv, NT, 3*HQ, CC);
        k_attn<<<BB*HH, 256>>>();
        // proj + bias + residual: [NT,256] @ [256,384]
        k_gemm<1,0,1,0><<<dim3(CC/64, NT/128), 256>>>(
            patt, Wo + (size_t)l*HQ*CC, bo + l*CC, px, px, NT, CC, HQ);
        k_ln<<<NT/8, 256>>>(px, pxn, ln2g + l*CC, ln2b + l*CC);
        // ff1 + bias + relu: [NT,384] @ [384,1536]
        k_gemm<1,1,0,0><<<dim3(FFF/64, NT/128), 256>>>(
            pxn, W1 + (size_t)l*CC*FFF, b1 + l*FFF, nullptr, ph, NT, FFF, CC);
        // ff2 + bias + residual: [NT,1536] @ [1536,384]
        k_gemm<1,0,1,0><<<dim3(CC/64, NT/128), 256>>>(
            ph, W2 + (size_t)l*FFF*CC, b2 + l*CC, px, px, NT, CC, FFF);
    }

    k_ln<<<NT/8, 256>>>(px, pxn, lnfg, lnfb);
    // lm head: [NT,384] @ [384,65] (N-guarded)
    k_gemm<1,0,0,1><<<dim3((VV + 63)/64, NT/128), 256>>>(
        pxn, Wlm, blm, nullptr, out, NT, VV, CC);

    k_nll<<<NT/8, 256>>>(out, tgt);
    if (out_size == 1)            k_loss<<<1, 256>>>(out, 0);
    else if (out_size > NT*VV)    k_loss<<<1, 256>>>(out, NT*VV);
}